// round 4
// baseline (speedup 1.0000x reference)
#include <cuda_runtime.h>

// DTCWT 1D forward, 3 levels, fully fused, POLYPHASE smem storage
// (even/odd split -> conflict-free stride-1 stencil reads at every level).
// x: [64, 1, 2^20] fp32.  Outputs flattened in tuple order:
// lo3 [64,131072], yh0 [64,524288], yh1 [64,2,262144], yh2 [64,2,131072].

#define T3   256
#define L_IN (1 << 20)
#define L1N  (L_IN / 2)
#define L2N  (L_IN / 4)
#define L3N  (L_IN / 8)

#define XS   2128            // x tile floats, base xbase = 8*o3-40
#define XH   (XS / 2)        // 1064 per phase
#define L1S  1060            // lo1 tile, base l1base = 4*o3-18
#define L1H  (L1S / 2)       // 530
#define L2S  524             // lo2 tile, base l2base = 2*o3-6
#define L2H  (L2S / 2)       // 262

// q-shift filters split into even/odd taps (exact fp32 of reference arrays)
#define DEF_QSHIFT \
    const float f0ae[7] = { 0.00325314f,  0.03466035f, -0.11720389f,  0.75614564f, \
                            0.01186609f,  0.02382538f, -0.00543948f}; \
    const float f0ao[7] = {-0.00388321f, -0.03887280f,  0.27529538f,  0.56881042f, \
                           -0.10671180f,  0.01702522f, -0.00455690f}
#define DEF_QHI \
    const float f1ae[7] = {-0.00455690f,  0.01702522f, -0.10671180f,  0.56881042f, \
                            0.27529538f, -0.03887280f, -0.00388321f}; \
    const float f1ao[7] = { 0.00543948f, -0.02382538f, -0.01186609f, -0.75614564f, \
                            0.11720389f, -0.03466035f, -0.00325314f}; \
    const float f1be[7] = {-0.00325314f, -0.03466035f,  0.11720389f, -0.75614564f, \
                           -0.01186609f, -0.02382538f,  0.00543948f}; \
    const float f1bo[7] = {-0.00388321f, -0.03887280f,  0.27529538f,  0.56881042f, \
                           -0.10671180f,  0.01702522f, -0.00455690f}

__global__ __launch_bounds__(256, 4)
void dtcwt3_poly_kernel(
    const float* __restrict__ x,
    float* __restrict__ out_lo3, float* __restrict__ out_hi1,
    float* __restrict__ out_yh1, float* __restrict__ out_yh2)
{
    __shared__ __align__(8) float sxe[XH], sxo[XH];
    __shared__ float s1e[L1H], s1o[L1H];
    __shared__ float s2e[L2H], s2o[L2H];

    const int tid = threadIdx.x;
    const int row = blockIdx.y;
    const int o3  = blockIdx.x * T3;
    const int xbase = 8 * o3 - 40;
    const float* __restrict__ xr = x + (size_t)row * L_IN;

    // ---- load x tile (float4) and deinterleave into even/odd phases ----
    #pragma unroll
    for (int it = 0; it < 3; it++) {
        int i4 = tid + 256 * it;
        if (i4 < XS / 4) {
            int g = xbase + 4 * i4;
            float4 v;
            if (g >= 0 && g + 3 < L_IN) {
                v = *reinterpret_cast<const float4*>(xr + g);
            } else {
                v.x = ((unsigned)(g    ) < (unsigned)L_IN) ? xr[g    ] : 0.f;
                v.y = ((unsigned)(g + 1) < (unsigned)L_IN) ? xr[g + 1] : 0.f;
                v.z = ((unsigned)(g + 2) < (unsigned)L_IN) ? xr[g + 2] : 0.f;
                v.w = ((unsigned)(g + 3) < (unsigned)L_IN) ? xr[g + 3] : 0.f;
            }
            *reinterpret_cast<float2*>(&sxe[2 * i4]) = make_float2(v.x, v.z);
            *reinterpret_cast<float2*>(&sxo[2 * i4]) = make_float2(v.y, v.w);
        }
    }
    __syncthreads();

    const int l1base = 4 * o3 - 18;

    // ---- level-1 lowpass -> s1e/s1o.  j = l1base+idx; e0 = idx+1.
    // lo1[j] = -.05*(E[e0]+E[e0+2]) + .6*E[e0+1] + .25*(O[e0]+O[e0+1])
    #pragma unroll
    for (int it = 0; it < 5; it++) {
        int idx = tid + 256 * it;
        if (idx < L1S) {
            int j = l1base + idx;
            float y = 0.f;
            if ((unsigned)j < (unsigned)L1N) {
                int e0 = idx + 1;
                y = fmaf(-0.05f, sxe[e0] + sxe[e0 + 2],
                    fmaf(0.6f, sxe[e0 + 1],
                         0.25f * (sxo[e0] + sxo[e0 + 1])));
            }
            if (idx & 1) s1o[idx >> 1] = y; else s1e[idx >> 1] = y;
        }
    }

    // ---- level-1 highpass -> yh0.  i = 4*o3+idx; ob = idx+18, eb = idx+19.
    // hi1 = c0*(O[ob]+O[ob+3]) + c2*(O[ob+1]+O[ob+2]) + c1*(E[eb]+E[eb+2]) + c3*E[eb+1]
    {
        float* __restrict__ dst = out_hi1 + (size_t)row * L1N + 4 * o3;
        #pragma unroll
        for (int it = 0; it < 4; it++) {
            int idx = tid + 256 * it;
            int ob = idx + 18, eb = idx + 19;
            float y = fmaf(-0.0107143f, sxo[ob] + sxo[ob + 3],
                      fmaf( 0.2607143f, sxo[ob + 1] + sxo[ob + 2],
                      fmaf( 0.0535714f, sxe[eb] + sxe[eb + 2],
                           -0.6071429f * sxe[eb + 1])));
            dst[idx] = y;
        }
    }
    __syncthreads();

    // ---- level-2 lowpass -> s2e/s2o.  g = l2base+idx; window base b = idx.
    {
        DEF_QSHIFT;
        #pragma unroll
        for (int it = 0; it < 3; it++) {
            int idx = tid + 256 * it;
            if (idx < L2S) {
                int g = (2 * o3 - 6) + idx;
                float y = 0.f;
                if ((unsigned)g < (unsigned)L2N) {
                    #pragma unroll
                    for (int k = 0; k < 7; k++) {
                        y = fmaf(s1e[idx + k], f0ae[k], y);
                        y = fmaf(s1o[idx + k], f0ao[k], y);
                    }
                }
                if (idx & 1) s2o[idx >> 1] = y; else s2e[idx >> 1] = y;
            }
        }
    }

    // ---- level-2 highpass a,b -> yh1.  i2 = 2*o3+idx; window base b = idx+6.
    {
        DEF_QHI;
        float* __restrict__ dsta = out_yh1 + (size_t)row * (2 * (size_t)L2N) + 2 * o3;
        float* __restrict__ dstb = dsta + L2N;
        #pragma unroll
        for (int it = 0; it < 2; it++) {
            int idx = tid + 256 * it;
            int b = idx + 6;
            float a = 0.f, bb = 0.f;
            #pragma unroll
            for (int k = 0; k < 7; k++) {
                float e = s1e[b + k], o = s1o[b + k];
                a  = fmaf(e, f1ae[k], a);  a  = fmaf(o, f1ao[k], a);
                bb = fmaf(e, f1be[k], bb); bb = fmaf(o, f1bo[k], bb);
            }
            dsta[idx] = a;
            dstb[idx] = bb;
        }
    }
    __syncthreads();

    // ---- level-3: lo, a, b.  i3 = o3+tid; window base = tid.
    {
        DEF_QSHIFT; DEF_QHI;
        float lo = 0.f, a = 0.f, bb = 0.f;
        #pragma unroll
        for (int k = 0; k < 7; k++) {
            float e = s2e[tid + k], o = s2o[tid + k];
            lo = fmaf(e, f0ae[k], lo); lo = fmaf(o, f0ao[k], lo);
            a  = fmaf(e, f1ae[k], a);  a  = fmaf(o, f1ao[k], a);
            bb = fmaf(e, f1be[k], bb); bb = fmaf(o, f1bo[k], bb);
        }
        (out_lo3 + (size_t)row * L3N + o3)[tid] = lo;
        float* dsta = out_yh2 + (size_t)row * (2 * (size_t)L3N) + o3;
        dsta[tid] = a;
        dsta[L3N + tid] = bb;
    }
}

extern "C" void kernel_launch(void* const* d_in, const int* in_sizes, int n_in,
                              void* d_out, int out_size)
{
    const float* x = (const float*)d_in[0];   // filters folded as immediates

    float* out = (float*)d_out;
    float* out_lo3 = out;                                   // 64 * 131072
    float* out_hi1 = out_lo3 + (size_t)64 * L3N;            // 64 * 524288
    float* out_yh1 = out_hi1 + (size_t)64 * L1N;            // 64 * 2 * 262144
    float* out_yh2 = out_yh1 + (size_t)64 * 2 * L2N;        // 64 * 2 * 131072

    dim3 grid(L3N / T3, 64);
    dtcwt3_poly_kernel<<<grid, 256>>>(x, out_lo3, out_hi1, out_yh1, out_yh2);
}

// round 5
// speedup vs baseline: 1.3492x; 1.3492x over previous
#include <cuda_runtime.h>

// DTCWT 1D forward, 3 levels, fused. Polyphase (even/odd) smem layout +
// pair-per-thread float2 window reads => conflict-free AND low instr count.
// x: [64,1,2^20] fp32. Outputs: lo3 [64,131072], yh0 [64,524288],
// yh1 [64,2,262144], yh2 [64,2,131072], flattened in that order.

#define T3   256
#define L_IN (1 << 20)
#define L1N  (L_IN / 2)
#define L2N  (L_IN / 4)
#define L3N  (L_IN / 8)

#define XH   1064   // per-phase x tile (2128 floats total), xbase = 8*o3-40
#define L1H  530    // per-phase lo1 tile (1060), l1base = 4*o3-18
#define L2H  262    // per-phase lo2 tile (524),  l2base = 2*o3-6

// q-shift filters split into even/odd taps (exact fp32 of reference arrays)
#define DEF_QLO \
    const float f0ae[7] = { 0.00325314f,  0.03466035f, -0.11720389f,  0.75614564f, \
                            0.01186609f,  0.02382538f, -0.00543948f}; \
    const float f0ao[7] = {-0.00388321f, -0.03887280f,  0.27529538f,  0.56881042f, \
                           -0.10671180f,  0.01702522f, -0.00455690f}
#define DEF_QHI \
    const float f1ae[7] = {-0.00455690f,  0.01702522f, -0.10671180f,  0.56881042f, \
                            0.27529538f, -0.03887280f, -0.00388321f}; \
    const float f1ao[7] = { 0.00543948f, -0.02382538f, -0.01186609f, -0.75614564f, \
                            0.11720389f, -0.03466035f, -0.00325314f}; \
    const float f1be[7] = {-0.00325314f, -0.03466035f,  0.11720389f, -0.75614564f, \
                           -0.01186609f, -0.02382538f,  0.00543948f}; \
    const float f1bo[7] = {-0.00388321f, -0.03887280f,  0.27529538f,  0.56881042f, \
                           -0.10671180f,  0.01702522f, -0.00455690f}

__global__ __launch_bounds__(256, 6)
void dtcwt3_pp_kernel(
    const float* __restrict__ x,
    float* __restrict__ out_lo3, float* __restrict__ out_hi1,
    float* __restrict__ out_yh1, float* __restrict__ out_yh2)
{
    __shared__ __align__(8) float sxe[XH], sxo[XH];
    __shared__ __align__(8) float s1e[L1H], s1o[L1H];
    __shared__ __align__(8) float s2e[L2H], s2o[L2H];

    const int tid = threadIdx.x;
    const int row = blockIdx.y;
    const int o3  = blockIdx.x * T3;
    const int xbase = 8 * o3 - 40;
    const float* __restrict__ xr = x + (size_t)row * L_IN;

    // ---- stage x tile (float4), deinterleave into even/odd phases ----
    #pragma unroll
    for (int it = 0; it < 3; it++) {
        int i4 = tid + 256 * it;
        if (i4 < XH / 2) {
            int g = xbase + 4 * i4;
            float4 v;
            if (g >= 0 && g + 3 < L_IN) {
                v = *reinterpret_cast<const float4*>(xr + g);
            } else {
                v.x = ((unsigned)(g    ) < (unsigned)L_IN) ? xr[g    ] : 0.f;
                v.y = ((unsigned)(g + 1) < (unsigned)L_IN) ? xr[g + 1] : 0.f;
                v.z = ((unsigned)(g + 2) < (unsigned)L_IN) ? xr[g + 2] : 0.f;
                v.w = ((unsigned)(g + 3) < (unsigned)L_IN) ? xr[g + 3] : 0.f;
            }
            *reinterpret_cast<float2*>(&sxe[2 * i4]) = make_float2(v.x, v.z);
            *reinterpret_cast<float2*>(&sxo[2 * i4]) = make_float2(v.y, v.w);
        }
    }
    __syncthreads();

    const float2* xe2 = reinterpret_cast<const float2*>(sxe);
    const float2* xo2 = reinterpret_cast<const float2*>(sxo);
    const int l1base = 4 * o3 - 18;

    // ---- level-1 lowpass: thread t -> lo1 local (2t, 2t+1) -> s1e[t], s1o[t]
    // lo1[idx]: e0=idx+1: -.05(E[e0]+E[e0+2]) + .6 E[e0+1] + .25(O[e0]+O[e0+1])
    #pragma unroll
    for (int it = 0; it < 3; it++) {
        int t = tid + 256 * it;
        if (t < L1H) {
            float2 ea = xe2[t], eb = xe2[t + 1], ec = xe2[t + 2];
            float2 oa = xo2[t], ob = xo2[t + 1];
            // E[2t+1]=ea.y  E[2t+2]=eb.x  E[2t+3]=eb.y  E[2t+4]=ec.x
            // O[2t+1]=oa.y  O[2t+2]=ob.x  O[2t+3]=ob.y
            float y0 = fmaf(-0.05f, ea.y + eb.y, fmaf(0.6f, eb.x, 0.25f * (oa.y + ob.x)));
            float y1 = fmaf(-0.05f, eb.x + ec.x, fmaf(0.6f, eb.y, 0.25f * (ob.x + ob.y)));
            int j0 = l1base + 2 * t;
            if ((unsigned)j0       >= (unsigned)L1N) y0 = 0.f;
            if ((unsigned)(j0 + 1) >= (unsigned)L1N) y1 = 0.f;
            s1e[t] = y0;
            s1o[t] = y1;
        }
    }

    // ---- level-1 highpass: thread t -> hi1 local (2t, 2t+1), t < 512
    // hi1[j]: ob=j+18, eb=j+19: -0.0107143(O[ob]+O[ob+3]) + 0.2607143(O[ob+1]+O[ob+2])
    //                            + 0.0535714(E[eb]+E[eb+2]) - 0.6071429 E[eb+1]
    {
        float2* dst2 = reinterpret_cast<float2*>(out_hi1 + (size_t)row * L1N + 4 * o3);
        #pragma unroll
        for (int it = 0; it < 2; it++) {
            int t = tid + 256 * it;
            float2 o9 = xo2[t + 9], o10 = xo2[t + 10], o11 = xo2[t + 11];
            float2 e9 = xe2[t + 9], e10 = xe2[t + 10], e11 = xe2[t + 11];
            // O[2t+18]=o9.x O[2t+19]=o9.y O[2t+20]=o10.x O[2t+21]=o10.y O[2t+22]=o11.x
            // E[2t+19]=e9.y E[2t+20]=e10.x E[2t+21]=e10.y E[2t+22]=e11.x
            float y0 = fmaf(-0.0107143f, o9.x + o10.y,
                       fmaf( 0.2607143f, o9.y + o10.x,
                       fmaf( 0.0535714f, e9.y + e10.y,
                            -0.6071429f * e10.x)));
            float y1 = fmaf(-0.0107143f, o9.y + o11.x,
                       fmaf( 0.2607143f, o10.x + o10.y,
                       fmaf( 0.0535714f, e10.x + e11.x,
                            -0.6071429f * e10.y)));
            dst2[t] = make_float2(y0, y1);
        }
    }
    __syncthreads();

    const float2* e12 = reinterpret_cast<const float2*>(s1e);
    const float2* o12 = reinterpret_cast<const float2*>(s1o);
    const int l2base = 2 * o3 - 6;

    // ---- level-2 lowpass: thread t -> lo2 local (2t, 2t+1) -> s2e[t], s2o[t]
    // lo2[idx] = sum_k f0ae[k] s1e[idx+k] + f0ao[k] s1o[idx+k]
    {
        DEF_QLO;
        #pragma unroll
        for (int it = 0; it < 2; it++) {
            int t = (it == 0) ? tid : 256 + tid;
            if (it == 0 || tid < L2H - 256) {
                float ve[8], vo[8];
                #pragma unroll
                for (int k = 0; k < 4; k++) {
                    float2 pe = e12[t + k], po = o12[t + k];
                    ve[2*k] = pe.x; ve[2*k+1] = pe.y;
                    vo[2*k] = po.x; vo[2*k+1] = po.y;
                }
                float y0 = 0.f, y1 = 0.f;
                #pragma unroll
                for (int k = 0; k < 7; k++) {
                    y0 = fmaf(ve[k],     f0ae[k], y0);
                    y0 = fmaf(vo[k],     f0ao[k], y0);
                    y1 = fmaf(ve[k + 1], f0ae[k], y1);
                    y1 = fmaf(vo[k + 1], f0ao[k], y1);
                }
                int g0 = l2base + 2 * t;
                if ((unsigned)g0       >= (unsigned)L2N) y0 = 0.f;
                if ((unsigned)(g0 + 1) >= (unsigned)L2N) y1 = 0.f;
                s2e[t] = y0;
                s2o[t] = y1;
            }
        }
    }

    // ---- level-2 highpass a,b: thread t -> yh1 local (2t, 2t+1), t < 256
    // window base b=j+6: reads s1e[2t+6 .. 2t+13]
    {
        DEF_QHI;
        int t = tid;
        float ve[8], vo[8];
        #pragma unroll
        for (int k = 0; k < 4; k++) {
            float2 pe = e12[t + 3 + k], po = o12[t + 3 + k];
            ve[2*k] = pe.x; ve[2*k+1] = pe.y;
            vo[2*k] = po.x; vo[2*k+1] = po.y;
        }
        float a0 = 0.f, a1 = 0.f, b0 = 0.f, b1 = 0.f;
        #pragma unroll
        for (int k = 0; k < 7; k++) {
            float e0 = ve[k], e1 = ve[k + 1], q0 = vo[k], q1 = vo[k + 1];
            a0 = fmaf(e0, f1ae[k], a0); a0 = fmaf(q0, f1ao[k], a0);
            a1 = fmaf(e1, f1ae[k], a1); a1 = fmaf(q1, f1ao[k], a1);
            b0 = fmaf(e0, f1be[k], b0); b0 = fmaf(q0, f1bo[k], b0);
            b1 = fmaf(e1, f1be[k], b1); b1 = fmaf(q1, f1bo[k], b1);
        }
        float* dsta = out_yh1 + (size_t)row * (2 * (size_t)L2N) + 2 * o3;
        reinterpret_cast<float2*>(dsta)[t]       = make_float2(a0, a1);
        reinterpret_cast<float2*>(dsta + L2N)[t] = make_float2(b0, b1);
    }
    __syncthreads();

    // ---- level-3: thread t < 128 -> outputs (2t, 2t+1) for lo, a, b ----
    if (tid < T3 / 2) {
        DEF_QLO; DEF_QHI;
        const float2* e22 = reinterpret_cast<const float2*>(s2e);
        const float2* o22 = reinterpret_cast<const float2*>(s2o);
        int t = tid;
        float ve[8], vo[8];
        #pragma unroll
        for (int k = 0; k < 4; k++) {
            float2 pe = e22[t + k], po = o22[t + k];
            ve[2*k] = pe.x; ve[2*k+1] = pe.y;
            vo[2*k] = po.x; vo[2*k+1] = po.y;
        }
        float l0 = 0.f, l1 = 0.f, a0 = 0.f, a1 = 0.f, b0 = 0.f, b1 = 0.f;
        #pragma unroll
        for (int k = 0; k < 7; k++) {
            float e0 = ve[k], e1 = ve[k + 1], q0 = vo[k], q1 = vo[k + 1];
            l0 = fmaf(e0, f0ae[k], l0); l0 = fmaf(q0, f0ao[k], l0);
            l1 = fmaf(e1, f0ae[k], l1); l1 = fmaf(q1, f0ao[k], l1);
            a0 = fmaf(e0, f1ae[k], a0); a0 = fmaf(q0, f1ao[k], a0);
            a1 = fmaf(e1, f1ae[k], a1); a1 = fmaf(q1, f1ao[k], a1);
            b0 = fmaf(e0, f1be[k], b0); b0 = fmaf(q0, f1bo[k], b0);
            b1 = fmaf(e1, f1be[k], b1); b1 = fmaf(q1, f1bo[k], b1);
        }
        float* dlo  = out_lo3 + (size_t)row * L3N + o3;
        float* dsta = out_yh2 + (size_t)row * (2 * (size_t)L3N) + o3;
        reinterpret_cast<float2*>(dlo )[t]       = make_float2(l0, l1);
        reinterpret_cast<float2*>(dsta)[t]       = make_float2(a0, a1);
        reinterpret_cast<float2*>(dsta + L3N)[t] = make_float2(b0, b1);
    }
}

extern "C" void kernel_launch(void* const* d_in, const int* in_sizes, int n_in,
                              void* d_out, int out_size)
{
    const float* x = (const float*)d_in[0];   // filters folded as immediates

    float* out = (float*)d_out;
    float* out_lo3 = out;                                   // 64 * 131072
    float* out_hi1 = out_lo3 + (size_t)64 * L3N;            // 64 * 524288
    float* out_yh1 = out_hi1 + (size_t)64 * L1N;            // 64 * 2 * 262144
    float* out_yh2 = out_yh1 + (size_t)64 * 2 * L2N;        // 64 * 2 * 131072

    dim3 grid(L3N / T3, 64);
    dtcwt3_pp_kernel<<<grid, 256>>>(x, out_lo3, out_hi1, out_yh1, out_yh2);
}